// round 6
// baseline (speedup 1.0000x reference)
#include <cuda_runtime.h>
#include <cuda_fp16.h>
#include <math.h>

// Problem constants (fixed by metadata)
#define MM      32768          // tokens
#define TOPK    2
#define NH      2048           // hidden
#define NF      4096           // ffn
#define NE      8              // experts
#define NA      (MM*TOPK)      // 65536 assignments
#define TILE_M  128
#define MAX_TILES 521          // ceil((65536 + 8*127)/128)
#define CAP     (MAX_TILES*TILE_M)   // 66688 padded rows

// -------- device scratch (static; no allocations allowed) --------
__device__ int    g_counts[NE];
__device__ int    g_cursor[NE];
__device__ int    g_off[NE+1];          // padded (128-aligned) segment offsets
__device__ int    g_row_ids[CAP];       // flat assignment id (m*TOPK+k) or -1
__device__ __half g_h[(size_t)CAP * (size_t)NF];   // fp16 intermediate, 546 MB

// ------------------------- setup kernels -------------------------
__global__ void k_zero() {
    int t = threadIdx.x;
    if (t < NE) { g_counts[t] = 0; g_cursor[t] = 0; }
}

__global__ void k_count_fill(const int* __restrict__ topks) {
    __shared__ int h[NE];
    int t = threadIdx.x;
    if (t < NE) h[t] = 0;
    __syncthreads();
    int stride = gridDim.x * blockDim.x;
    int i = blockIdx.x * blockDim.x + t;
    for (int p = i; p < CAP; p += stride) g_row_ids[p] = -1;
    for (int p = i; p < NA; p += stride) atomicAdd(&h[topks[p]], 1);
    __syncthreads();
    if (t < NE && h[t]) atomicAdd(&g_counts[t], h[t]);
}

__global__ void k_offsets() {
    int s = 0;
    g_off[0] = 0;
    for (int e = 0; e < NE; e++) {
        s += (g_counts[e] + (TILE_M - 1)) & ~(TILE_M - 1);
        g_off[e + 1] = s;
    }
}

__global__ void k_scatter(const int* __restrict__ topks) {
    int stride = gridDim.x * blockDim.x;
    int i = blockIdx.x * blockDim.x + threadIdx.x;
    for (int p = i; p < NA; p += stride) {
        int e = topks[p];
        int pos = g_off[e] + atomicAdd(&g_cursor[e], 1);
        g_row_ids[pos] = p;   // row value independent of intra-expert order
    }
}

// ---------------- Kernel A: h = silu(x@w1) * (x@w3), fp16 out ----------------
// CTA tile: 128 rows x 64 ffn cols, K-step 16. 256 threads, 8x4 per-thread (g,u).
// FFN split into 2 halves of 32 col-tiles so live w1+w3 slab = 33.5MB (L2-resident).
__global__ __launch_bounds__(256, 2)
void kA(const float* __restrict__ x,
        const float* __restrict__ w1g,
        const float* __restrict__ w3g)
{
    const int HALF = MAX_TILES * 32;
    int c    = blockIdx.x;
    int half = c / HALF;
    int cc   = c - half * HALF;
    int rt   = cc >> 5;               // row tile (consecutive blocks share rt)
    int ct   = (half << 5) + (cc & 31);
    int rowstart = rt * TILE_M;
    if (rowstart >= g_off[NE]) return;
    int e = 0;
    while (e < NE - 1 && rowstart >= g_off[e + 1]) e++;

    __shared__ int   tok[TILE_M];
    __shared__ float xs [2][16][128];
    __shared__ float w1s[2][16][64];
    __shared__ float w3s[2][16][64];

    int t = threadIdx.x;
    if (t < TILE_M) {
        int f = g_row_ids[rowstart + t];
        tok[t] = (f < 0) ? 0 : (f >> 1);
    }
    __syncthreads();

    int tx = t & 15;      // 4 cols each
    int ty = t >> 4;      // 8 rows each
    int n0 = ct * 64;
    const float* w1e = w1g + (size_t)e * NH * NF + n0;
    const float* w3e = w3g + (size_t)e * NH * NF + n0;

    float accg[8][4], accu[8][4];
#pragma unroll
    for (int i = 0; i < 8; i++)
#pragma unroll
        for (int j = 0; j < 4; j++) { accg[i][j] = 0.f; accu[i][j] = 0.f; }

    float4 rx[2], rw1, rw3;
    const int xrow0 = t >> 2, xkq0 = (t & 3) << 2;        // x stage indices
    const int xrow1 = (t + 256) >> 2, xkq1 = ((t + 256) & 3) << 2;
    const int wkr = t >> 4, wnq = (t & 15) << 2;          // weight stage indices

    auto LDG = [&](int k0) {
        rx[0] = *(const float4*)(x + (size_t)tok[xrow0] * NH + k0 + xkq0);
        rx[1] = *(const float4*)(x + (size_t)tok[xrow1] * NH + k0 + xkq1);
        rw1   = *(const float4*)(w1e + (size_t)(k0 + wkr) * NF + wnq);
        rw3   = *(const float4*)(w3e + (size_t)(k0 + wkr) * NF + wnq);
    };
    auto STS = [&](int s) {
        xs[s][xkq0+0][xrow0] = rx[0].x; xs[s][xkq0+1][xrow0] = rx[0].y;
        xs[s][xkq0+2][xrow0] = rx[0].z; xs[s][xkq0+3][xrow0] = rx[0].w;
        xs[s][xkq1+0][xrow1] = rx[1].x; xs[s][xkq1+1][xrow1] = rx[1].y;
        xs[s][xkq1+2][xrow1] = rx[1].z; xs[s][xkq1+3][xrow1] = rx[1].w;
        *(float4*)&w1s[s][wkr][wnq] = rw1;
        *(float4*)&w3s[s][wkr][wnq] = rw3;
    };

    LDG(0); STS(0); __syncthreads();
    const int NKT = NH / 16;   // 128
    for (int kt = 0; kt < NKT; kt++) {
        int cur = kt & 1;
        if (kt + 1 < NKT) LDG((kt + 1) * 16);
#pragma unroll
        for (int kk = 0; kk < 16; kk++) {
            float a[8];
#pragma unroll
            for (int mi = 0; mi < 8; mi++) a[mi] = xs[cur][kk][ty * 8 + mi];
            float b1[4], b3[4];
#pragma unroll
            for (int ni = 0; ni < 4; ni++) {
                b1[ni] = w1s[cur][kk][tx * 4 + ni];
                b3[ni] = w3s[cur][kk][tx * 4 + ni];
            }
#pragma unroll
            for (int mi = 0; mi < 8; mi++)
#pragma unroll
                for (int ni = 0; ni < 4; ni++) {
                    accg[mi][ni] += a[mi] * b1[ni];
                    accu[mi][ni] += a[mi] * b3[ni];
                }
        }
        if (kt + 1 < NKT) { __syncthreads(); STS(cur ^ 1); __syncthreads(); }
    }

    // epilogue: silu(g)*u -> fp16 (padded rows harmlessly computed & stored)
#pragma unroll
    for (int mi = 0; mi < 8; mi++) {
        int r = ty * 8 + mi;
        float s[4];
#pragma unroll
        for (int ni = 0; ni < 4; ni++) {
            float g = accg[mi][ni];
            s[ni] = g / (1.f + __expf(-g)) * accu[mi][ni];
        }
        union { uint2 u; __half2 h[2]; } pk;
        pk.h[0] = __floats2half2_rn(s[0], s[1]);
        pk.h[1] = __floats2half2_rn(s[2], s[3]);
        *(uint2*)(g_h + (size_t)(rowstart + r) * NF + n0 + tx * 4) = pk.u;
    }
}

// ---------------- Kernel B: out = h @ w2 (h fp16, acc fp32) ----------------
// CTA tile: 128 rows x 64 hidden cols, K-step 16 over FFN=4096.
__global__ __launch_bounds__(256, 2)
void kB(const float* __restrict__ w2g, float* __restrict__ out)
{
    int c  = blockIdx.x;
    int rt = c >> 5;            // 2048/64 = 32 col tiles; consecutive blocks share rt
    int ct = c & 31;
    int rowstart = rt * TILE_M;
    if (rowstart >= g_off[NE]) return;
    int e = 0;
    while (e < NE - 1 && rowstart >= g_off[e + 1]) e++;

    __shared__ int   flat[TILE_M];
    __shared__ float hs [2][16][128];
    __shared__ float w2s[2][16][64];

    int t = threadIdx.x;
    if (t < TILE_M) flat[t] = g_row_ids[rowstart + t];
    __syncthreads();

    int tx = t & 15;
    int ty = t >> 4;
    int n0 = ct * 64;
    const float*  w2e  = w2g + (size_t)e * NF * NH + n0;
    const __half* hrow = g_h + (size_t)rowstart * NF;

    float acc[8][4];
#pragma unroll
    for (int i = 0; i < 8; i++)
#pragma unroll
        for (int j = 0; j < 4; j++) acc[i][j] = 0.f;

    uint4  rh; float4 rw;
    const int hrow_i = t >> 1, hq = (t & 1) * 8;    // 8 halfs (16B) each
    const int wkr = t >> 4, wnq = (t & 15) << 2;

    auto LDG = [&](int k0) {
        rh = *(const uint4*)(hrow + (size_t)hrow_i * NF + k0 + hq);
        rw = *(const float4*)(w2e + (size_t)(k0 + wkr) * NH + wnq);
    };
    auto STS = [&](int s) {
        const __half2* hh = (const __half2*)&rh;
#pragma unroll
        for (int j = 0; j < 4; j++) {
            float2 f = __half22float2(hh[j]);
            hs[s][hq + 2 * j + 0][hrow_i] = f.x;
            hs[s][hq + 2 * j + 1][hrow_i] = f.y;
        }
        *(float4*)&w2s[s][wkr][wnq] = rw;
    };

    LDG(0); STS(0); __syncthreads();
    const int NKT = NF / 16;   // 256
    for (int kt = 0; kt < NKT; kt++) {
        int cur = kt & 1;
        if (kt + 1 < NKT) LDG((kt + 1) * 16);
#pragma unroll
        for (int kk = 0; kk < 16; kk++) {
            float a[8];
#pragma unroll
            for (int mi = 0; mi < 8; mi++) a[mi] = hs[cur][kk][ty * 8 + mi];
            float b[4];
#pragma unroll
            for (int ni = 0; ni < 4; ni++) b[ni] = w2s[cur][kk][tx * 4 + ni];
#pragma unroll
            for (int mi = 0; mi < 8; mi++)
#pragma unroll
                for (int ni = 0; ni < 4; ni++)
                    acc[mi][ni] += a[mi] * b[ni];
        }
        if (kt + 1 < NKT) { __syncthreads(); STS(cur ^ 1); __syncthreads(); }
    }

#pragma unroll
    for (int mi = 0; mi < 8; mi++) {
        int r = ty * 8 + mi;
        int f = flat[r];
        if (f < 0) continue;
        float4 v = make_float4(acc[mi][0], acc[mi][1], acc[mi][2], acc[mi][3]);
        *(float4*)(out + (size_t)f * NH + n0 + tx * 4) = v;
    }
}

// ------------------------------ launch ------------------------------
extern "C" void kernel_launch(void* const* d_in, const int* in_sizes, int n_in,
                              void* d_out, int out_size)
{
    const float* x     = (const float*)d_in[0];   // [32768, 2048]
    const int*   topks = (const int*)  d_in[1];   // [32768, 2]
    const float* w1    = (const float*)d_in[2];   // [8, 2048, 4096]
    const float* w2    = (const float*)d_in[3];   // [8, 4096, 2048]
    const float* w3    = (const float*)d_in[4];   // [8, 2048, 4096]
    float* out = (float*)d_out;                   // [32768, 2, 2048]

    k_zero      <<<1, 32>>>();
    k_count_fill<<<256, 256>>>(topks);
    k_offsets   <<<1, 1>>>();
    k_scatter   <<<256, 256>>>(topks);
    kA<<<MAX_TILES * 64, 256>>>(x, w1, w3);
    kB<<<MAX_TILES * 32, 256>>>(w2, out);
}

// round 10
// speedup vs baseline: 3.3644x; 3.3644x over previous
#include <cuda_runtime.h>
#include <cuda_fp16.h>
#include <stdint.h>
#include <math.h>

// ---------------- problem constants ----------------
#define MM      32768
#define TOPK    2
#define NH      2048
#define NF      4096
#define NE      8
#define NA      (MM*TOPK)
#define TILE_M  128
#define MAX_TILES 521
#define CAP     (MAX_TILES*TILE_M)     // 66688 padded rows

// ---------------- device scratch (R5-proven footprint: ~547MB) ----------------
__device__ int    g_counts[NE];
__device__ int    g_cursor[NE];
__device__ int    g_off[NE+1];
__device__ int    g_row_ids[CAP];
__device__ __align__(16) __half g_h[(size_t)CAP * (size_t)NF];   // fp16 intermediate

// ---------------- mma.sync m16n8k16 (fp16 in, fp32 acc) ----------------
#define MMA(c,a,b) \
    asm volatile("mma.sync.aligned.m16n8k16.row.col.f32.f16.f16.f32 " \
        "{%0,%1,%2,%3}, {%4,%5,%6,%7}, {%8,%9}, {%0,%1,%2,%3};" \
        : "+f"((c)[0]),"+f"((c)[1]),"+f"((c)[2]),"+f"((c)[3]) \
        : "r"((a)[0]),"r"((a)[1]),"r"((a)[2]),"r"((a)[3]),"r"((b)[0]),"r"((b)[1]))

__device__ __forceinline__ uint32_t pack2(__half lo, __half hi) {
    __half2 h = __halves2half2(lo, hi);
    return *(uint32_t*)&h;
}

// A smem: [m=128][k=16] halfs, row stride 24 halfs (48B) -> conflict-free a-frag LDS
#define ASTR 24
// B smem: [k=16][n=128] halfs, row stride 136 halfs (272B) -> conflict-free b-frag LDS
#define BSTR 136

// ---------------- setup kernels (verbatim from R5, proven) ----------------
__global__ void k_zero() {
    int t = threadIdx.x;
    if (t < NE) { g_counts[t] = 0; g_cursor[t] = 0; }
}
__global__ void k_count_fill(const int* __restrict__ topks) {
    __shared__ int h[NE];
    int t = threadIdx.x;
    if (t < NE) h[t] = 0;
    __syncthreads();
    int stride = gridDim.x * blockDim.x;
    int i = blockIdx.x * blockDim.x + t;
    for (int p = i; p < CAP; p += stride) g_row_ids[p] = -1;
    for (int p = i; p < NA; p += stride) atomicAdd(&h[topks[p]], 1);
    __syncthreads();
    if (t < NE && h[t]) atomicAdd(&g_counts[t], h[t]);
}
__global__ void k_offsets() {
    int s = 0; g_off[0] = 0;
    for (int e = 0; e < NE; e++) {
        s += (g_counts[e] + (TILE_M - 1)) & ~(TILE_M - 1);
        g_off[e + 1] = s;
    }
}
__global__ void k_scatter(const int* __restrict__ topks) {
    int stride = gridDim.x * blockDim.x;
    int i = blockIdx.x * blockDim.x + threadIdx.x;
    for (int p = i; p < NA; p += stride) {
        int e = topks[p];
        int pos = g_off[e] + atomicAdd(&g_cursor[e], 1);
        g_row_ids[pos] = p;
    }
}

// ---------------- GEMM A: h = silu(x@w1) * (x@w3) ----------------
// CTA 128M x 128N, K-step 16, fp32 sources converted to fp16 in registers.
// 8 warps: wm=wid&1 (64 rows), wn=wid>>1 (32 cols). Weights read in NATIVE
// layout (w1[e][h][f]: row=k, contiguous n) -> B smem [k][n], no transpose.
__global__ __launch_bounds__(256, 1)
void gA(const float* __restrict__ x,
        const float* __restrict__ w1,
        const float* __restrict__ w3)
{
    __shared__ __half Asm [2][TILE_M * ASTR];    // 12288 B
    __shared__ __half B1sm[2][16 * BSTR];        //  8704 B
    __shared__ __half B3sm[2][16 * BSTR];        //  8704 B
    __shared__ int    tok[TILE_M];

    int tid = threadIdx.x, lane = tid & 31, wid = tid >> 5;
    int wm = wid & 1, wn = wid >> 1;
    int g = lane >> 2, qi = lane & 3;
    int rt = blockIdx.x, ct = blockIdx.y;        // grid (521, 32), ct-major in time
    int rowstart = rt * TILE_M;
    if (rowstart >= g_off[NE]) return;
    int e = 0;
    while (e < NE - 1 && rowstart >= g_off[e + 1]) e++;
    int n0 = ct * 128;

    if (tid < TILE_M) {
        int f = g_row_ids[rowstart + tid];
        tok[tid] = (f < 0) ? 0 : (f >> 1);
    }
    __syncthreads();

    const float* w1e = w1 + (size_t)e * NH * NF + n0;
    const float* w3e = w3 + (size_t)e * NH * NF + n0;

    float accg[4][4][4], accu[4][4][4];
#pragma unroll
    for (int i = 0; i < 4; i++)
#pragma unroll
        for (int j = 0; j < 4; j++)
#pragma unroll
            for (int q = 0; q < 4; q++) { accg[i][j][q] = 0.f; accu[i][j][q] = 0.f; }

    // prefetch registers: A 2 chunks, B1 2, B3 2 (float4 each)
    float4 pf[6];
    // A chunks: c in {tid, tid+256} of 512: row=c>>2, kq=(c&3)*4
    const int ar0 = tid >> 2,         ak0 = (tid & 3) * 4;
    const int ar1 = (tid + 256) >> 2, ak1 = ((tid + 256) & 3) * 4;
    // B chunks: c in {tid, tid+256} of 512: row=c>>5, j=c&31 (float4 cols)
    const int br0 = tid >> 5,         bj0 = (tid & 31) * 4;
    const int br1 = (tid + 256) >> 5, bj1 = ((tid + 256) & 31) * 4;

    auto LDGr = [&](int kt) {
        int k0 = kt * 16;
        pf[0] = *(const float4*)(x + (size_t)tok[ar0] * NH + k0 + ak0);
        pf[1] = *(const float4*)(x + (size_t)tok[ar1] * NH + k0 + ak1);
        pf[2] = *(const float4*)(w1e + (size_t)(k0 + br0) * NF + bj0);
        pf[3] = *(const float4*)(w1e + (size_t)(k0 + br1) * NF + bj1);
        pf[4] = *(const float4*)(w3e + (size_t)(k0 + br0) * NF + bj0);
        pf[5] = *(const float4*)(w3e + (size_t)(k0 + br1) * NF + bj1);
    };
    auto cvt = [&](float4 v) {
        __half2 h0 = __floats2half2_rn(v.x, v.y);
        __half2 h1 = __floats2half2_rn(v.z, v.w);
        return make_uint2(*(uint32_t*)&h0, *(uint32_t*)&h1);
    };
    auto STSb = [&](int buf) {
        *(uint2*)&Asm [buf][ar0 * ASTR + ak0] = cvt(pf[0]);
        *(uint2*)&Asm [buf][ar1 * ASTR + ak1] = cvt(pf[1]);
        *(uint2*)&B1sm[buf][br0 * BSTR + bj0] = cvt(pf[2]);
        *(uint2*)&B1sm[buf][br1 * BSTR + bj1] = cvt(pf[3]);
        *(uint2*)&B3sm[buf][br0 * BSTR + bj0] = cvt(pf[4]);
        *(uint2*)&B3sm[buf][br1 * BSTR + bj1] = cvt(pf[5]);
    };

    LDGr(0); STSb(0); __syncthreads();
    const int KT = NH / 16;   // 128
    for (int kt = 0; kt < KT; kt++) {
        if (kt + 1 < KT) LDGr(kt + 1);
        int buf = kt & 1;
        uint32_t a[4][4];
#pragma unroll
        for (int mt = 0; mt < 4; mt++) {
            int r = wm * 64 + mt * 16 + g;
            a[mt][0] = *(const uint32_t*)&Asm[buf][ r      * ASTR + 2 * qi];
            a[mt][1] = *(const uint32_t*)&Asm[buf][(r + 8) * ASTR + 2 * qi];
            a[mt][2] = *(const uint32_t*)&Asm[buf][ r      * ASTR + 8 + 2 * qi];
            a[mt][3] = *(const uint32_t*)&Asm[buf][(r + 8) * ASTR + 8 + 2 * qi];
        }
#pragma unroll
        for (int nn = 0; nn < 4; nn++) {
            int col = wn * 32 + nn * 8 + g;
            uint32_t b1[2], b3[2];
            b1[0] = pack2(B1sm[buf][(2*qi)   * BSTR + col], B1sm[buf][(2*qi+1) * BSTR + col]);
            b1[1] = pack2(B1sm[buf][(2*qi+8) * BSTR + col], B1sm[buf][(2*qi+9) * BSTR + col]);
            b3[0] = pack2(B3sm[buf][(2*qi)   * BSTR + col], B3sm[buf][(2*qi+1) * BSTR + col]);
            b3[1] = pack2(B3sm[buf][(2*qi+8) * BSTR + col], B3sm[buf][(2*qi+9) * BSTR + col]);
#pragma unroll
            for (int mt = 0; mt < 4; mt++) {
                MMA(accg[mt][nn], a[mt], b1);
                MMA(accu[mt][nn], a[mt], b3);
            }
        }
        if (kt + 1 < KT) { STSb(buf ^ 1); __syncthreads(); }
    }

    // epilogue: silu(g)*u -> fp16 h
    int colbase = n0 + wn * 32 + qi * 2;
#pragma unroll
    for (int mt = 0; mt < 4; mt++)
#pragma unroll
        for (int rs = 0; rs < 2; rs++) {
            int row = rowstart + wm * 64 + mt * 16 + g + rs * 8;
            __half* dst = g_h + (size_t)row * NF + colbase;
#pragma unroll
            for (int nn = 0; nn < 4; nn++) {
                float g0 = accg[mt][nn][rs * 2],     u0 = accu[mt][nn][rs * 2];
                float g1 = accg[mt][nn][rs * 2 + 1], u1 = accu[mt][nn][rs * 2 + 1];
                float s0 = g0 / (1.f + __expf(-g0)) * u0;
                float s1 = g1 / (1.f + __expf(-g1)) * u1;
                *(__half2*)(dst + nn * 8) = __floats2half2_rn(s0, s1);
            }
        }
}

// ---------------- GEMM B: out = h @ w2 ----------------
// A from g_h (already fp16), B = w2 native [e][f][h]: row=k(f), contiguous n(h).
__global__ __launch_bounds__(256, 2)
void gB(const float* __restrict__ w2, float* __restrict__ out)
{
    __shared__ __half Asm2[2][TILE_M * ASTR];    // 12288 B
    __shared__ __half Bsm2[2][16 * BSTR];        //  8704 B

    int tid = threadIdx.x, lane = tid & 31, wid = tid >> 5;
    int wm = wid & 1, wn = wid >> 1;
    int g = lane >> 2, qi = lane & 3;
    int rt = blockIdx.x, ct = blockIdx.y;        // grid (521, 16)
    int rowstart = rt * TILE_M;
    if (rowstart >= g_off[NE]) return;
    int e = 0;
    while (e < NE - 1 && rowstart >= g_off[e + 1]) e++;
    int n0 = ct * 128;

    const __half* Ab  = g_h + (size_t)rowstart * NF;
    const float*  w2e = w2 + (size_t)e * NF * NH + n0;

    float acc[4][4][4];
#pragma unroll
    for (int i = 0; i < 4; i++)
#pragma unroll
        for (int j = 0; j < 4; j++)
#pragma unroll
            for (int q = 0; q < 4; q++) acc[i][j][q] = 0.f;

    uint4  pa;        // A: 256 uint4 chunks (16B of halfs): row=c>>1, q=c&1
    float4 pb[2];     // B: 512 float4 chunks: row=c>>5, j=c&31
    const int aro = tid >> 1,         aqo = (tid & 1) * 8;
    const int br0 = tid >> 5,         bj0 = (tid & 31) * 4;
    const int br1 = (tid + 256) >> 5, bj1 = ((tid + 256) & 31) * 4;

    auto LDGr = [&](int kt) {
        int k0 = kt * 16;
        pa    = *(const uint4*) (Ab  + (size_t)aro * NF + k0 + aqo);
        pb[0] = *(const float4*)(w2e + (size_t)(k0 + br0) * NH + bj0);
        pb[1] = *(const float4*)(w2e + (size_t)(k0 + br1) * NH + bj1);
    };
    auto cvt = [&](float4 v) {
        __half2 h0 = __floats2half2_rn(v.x, v.y);
        __half2 h1 = __floats2half2_rn(v.z, v.w);
        return make_uint2(*(uint32_t*)&h0, *(uint32_t*)&h1);
    };
    auto STSb = [&](int buf) {
        *(uint4*)&Asm2[buf][aro * ASTR + aqo] = pa;
        *(uint2*)&Bsm2[buf][br0 * BSTR + bj0] = cvt(pb[0]);
        *(uint2*)&Bsm2[buf][br1 * BSTR + bj1] = cvt(pb[1]);
    };

    LDGr(0); STSb(0); __syncthreads();
    const int KT = NF / 16;   // 256
    for (int kt = 0; kt < KT; kt++) {
        if (kt + 1 < KT) LDGr(kt + 1);
        int buf = kt & 1;
        uint32_t a[4][4];
#pragma unroll
        for (int mt = 0; mt < 4; mt++) {
            int r = wm * 64 + mt * 16 + g;
            a[mt][0] = *(const uint32_t*)&Asm2[buf][ r      * ASTR + 2 * qi];
            a[mt][1] = *(const uint32_t*)&Asm2[buf][(r + 8) * ASTR + 2 * qi];
            a[mt][2] = *(const uint32_t*)&Asm2[buf][ r      * ASTR + 8 + 2 * qi];
            a[mt][3] = *(const uint32_t*)&Asm2[buf][(r + 8) * ASTR + 8 + 2 * qi];
        }
#pragma unroll
        for (int nn = 0; nn < 4; nn++) {
            int col = wn * 32 + nn * 8 + g;
            uint32_t b[2];
            b[0] = pack2(Bsm2[buf][(2*qi)   * BSTR + col], Bsm2[buf][(2*qi+1) * BSTR + col]);
            b[1] = pack2(Bsm2[buf][(2*qi+8) * BSTR + col], Bsm2[buf][(2*qi+9) * BSTR + col]);
#pragma unroll
            for (int mt = 0; mt < 4; mt++) MMA(acc[mt][nn], a[mt], b);
        }
        if (kt + 1 < KT) { STSb(buf ^ 1); __syncthreads(); }
    }

    int colbase = n0 + wn * 32 + qi * 2;
#pragma unroll
    for (int mt = 0; mt < 4; mt++)
#pragma unroll
        for (int rs = 0; rs < 2; rs++) {
            int lrow = wm * 64 + mt * 16 + g + rs * 8;
            int f = g_row_ids[rowstart + lrow];
            if (f < 0) continue;
            float* dst = out + (size_t)f * NH + colbase;
#pragma unroll
            for (int nn = 0; nn < 4; nn++) {
                float2 v = make_float2(acc[mt][nn][rs * 2], acc[mt][nn][rs * 2 + 1]);
                *(float2*)(dst + nn * 8) = v;
            }
        }
}

// ---------------- launch ----------------
extern "C" void kernel_launch(void* const* d_in, const int* in_sizes, int n_in,
                              void* d_out, int out_size)
{
    const float* x     = (const float*)d_in[0];
    const int*   topks = (const int*)  d_in[1];
    const float* w1    = (const float*)d_in[2];
    const float* w2    = (const float*)d_in[3];
    const float* w3    = (const float*)d_in[4];
    float* out = (float*)d_out;

    k_zero      <<<1, 32>>>();
    k_count_fill<<<256, 256>>>(topks);
    k_offsets   <<<1, 1>>>();
    k_scatter   <<<256, 256>>>(topks);
    gA<<<dim3(MAX_TILES, 32), 256>>>(x, w1, w3);
    gB<<<dim3(MAX_TILES, 16), 256>>>(w2, out);
}